// round 12
// baseline (speedup 1.0000x reference)
#include <cuda_runtime.h>
#include <cuda_bf16.h>
#include <cstddef>

// Problem constants
#define NUM_C 1000
#define Dd    128
#define Mm    64
#define Bb    64
#define Ll    512
#define NROWS (Bb * Ll)   // 32768
#define CH    16          // scan: steps staged per chunk

typedef unsigned long long u64;

// Scratch (static device globals — allocation-free)
__device__ float g_w[NROWS * Mm];
__device__ float g_e[NROWS * Dd];      // NOTE: holds NEGATED erase gate (-e); scan-only consumer
__device__ float g_a[NROWS * Dd];
__device__ float g_read[NROWS * Dd];
// j-pair packed Wf, lane-dense layout (see k_prep)
__device__ u64 g_WfP [(Dd / 2) * Dd];
__device__ u64 g_WfkP[(Dd / 2) * Dd];

__device__ __forceinline__ float sigmoidf_(float x) {
    return 1.0f / (1.0f + __expf(-x));
}
__device__ __forceinline__ u64 bcast2(float x) {
    u64 r; asm("mov.b64 %0, {%1,%1};" : "=l"(r) : "f"(x)); return r;
}
__device__ __forceinline__ u64 pack2(float x, float y) {
    u64 r; asm("mov.b64 %0, {%1,%2};" : "=l"(r) : "f"(x), "f"(y)); return r;
}
__device__ __forceinline__ u64 fma2(u64 a, u64 b, u64 c) {
    u64 d; asm("fma.rn.f32x2 %0, %1, %2, %3;" : "=l"(d) : "l"(a), "l"(b), "l"(c)); return d;
}
__device__ __forceinline__ u64 add2(u64 a, u64 b) {
    u64 d; asm("add.rn.f32x2 %0, %1, %2;" : "=l"(d) : "l"(a), "l"(b)); return d;
}
__device__ __forceinline__ float2 unpk(u64 v) {
    float2 f; asm("mov.b64 {%0,%1}, %2;" : "=f"(f.x), "=f"(f.y) : "l"(v)); return f;
}
__device__ __forceinline__ float hsum2(u64 v) {
    float2 f = unpk(v); return f.x + f.y;
}

// ---------------------------------------------------------------------------
// Kernel 0: repack Wf into j-pair packed, lane-dense layout (both halves).
// ---------------------------------------------------------------------------
__global__ __launch_bounds__(256) void k_prep(const float* __restrict__ Wf)
{
    int idx = blockIdx.x * 256 + threadIdx.x;      // 0 .. 8191
    if (idx < (Dd / 2) * Dd) {
        int jp = idx >> 7;
        int s  = idx & 127;
        int col;
        if (s < 64) col = 4 * (s >> 1) + (s & 1);
        else { int s2 = s - 64; col = 4 * (s2 >> 1) + 2 + (s2 & 1); }
        g_WfP [idx] = pack2(Wf[(size_t)(2 * jp)      * Dd + col],
                            Wf[(size_t)(2 * jp + 1)  * Dd + col]);
        g_WfkP[idx] = pack2(Wf[(size_t)(Dd + 2 * jp)     * Dd + col],
                            Wf[(size_t)(Dd + 2 * jp + 1) * Dd + col]);
    }
}

// ---------------------------------------------------------------------------
// Kernel 1a: logits + softmax -> w.   512 threads, 64 rows/block.
// ---------------------------------------------------------------------------
__global__ __launch_bounds__(512, 2) void k_w(
    const int* __restrict__ q,
    const float* __restrict__ Ek,
    const float* __restrict__ Mk)
{
    extern __shared__ float sm[];
    float* sK   = sm;                 // [64][Dd]  32 KB
    float* sMkP = sm + 64 * Dd;       // [64 jp][64 slots float2]  32 KB

    const int tid  = threadIdx.x;
    const int row0 = blockIdx.x * 64;

    for (int i = tid; i < 64 * (Dd / 4); i += 512) {
        int rr = i >> 5;
        int c4 = i & 31;
        int qi = q[row0 + rr];
        ((float4*)(sK + rr * Dd))[c4] = ((const float4*)(Ek + (size_t)qi * Dd))[c4];
    }
    for (int i = tid; i < Mm * (Dd / 2); i += 512) {
        int s  = i & 63;
        int jp = i >> 6;
        ((float2*)sMkP)[jp * 64 + s] = *(const float2*)(Mk + (size_t)s * Dd + 2 * jp);
    }
    __syncthreads();

    const int wid = tid >> 5;
    const int cg  = tid & 31;

    u64 acc0[4], acc1[4];
    #pragma unroll
    for (int i = 0; i < 4; i++) { acc0[i] = 0ull; acc1[i] = 0ull; }

    for (int jp = 0; jp < Dd / 2; jp++) {
        ulonglong2 mk2 = ((const ulonglong2*)(sMkP + jp * 128))[cg];
        #pragma unroll
        for (int i = 0; i < 4; i++) {
            u64 k2 = *(const u64*)(sK + (wid * 4 + i) * Dd + 2 * jp);
            acc0[i] = fma2(k2, mk2.x, acc0[i]);
            acc1[i] = fma2(k2, mk2.y, acc1[i]);
        }
    }
    #pragma unroll
    for (int i = 0; i < 4; i++) {
        float l0 = hsum2(acc0[i]);
        float l1 = hsum2(acc1[i]);
        float mx = fmaxf(l0, l1);
        #pragma unroll
        for (int o = 16; o > 0; o >>= 1)
            mx = fmaxf(mx, __shfl_xor_sync(0xffffffffu, mx, o));
        float e0 = __expf(l0 - mx);
        float e1 = __expf(l1 - mx);
        float s = e0 + e1;
        #pragma unroll
        for (int o = 16; o > 0; o >>= 1)
            s += __shfl_xor_sync(0xffffffffu, s, o);
        float inv = 1.0f / s;
        *(float2*)(g_w + (size_t)(row0 + wid * 4 + i) * Mm + 2 * cg) =
            make_float2(e0 * inv, e1 * inv);
    }
}

// ---------------------------------------------------------------------------
// Kernel 1b: e = sigmoid(v We + be) [stored NEGATED], a = tanh(v Wa + ba).
// R5-proven structure: float4 weight loads + pack2.
// ---------------------------------------------------------------------------
__global__ __launch_bounds__(256, 4) void k_ea(
    const int* __restrict__ q, const int* __restrict__ r,
    const float* __restrict__ Ev,
    const float* __restrict__ We, const float* __restrict__ be,
    const float* __restrict__ Wa, const float* __restrict__ ba)
{
    extern __shared__ float sm[];
    float* sV = sm;   // [32][Dd]  16 KB

    const int tid  = threadIdx.x;
    const int row0 = blockIdx.x * 32;

    for (int i = tid; i < 32 * (Dd / 4); i += 256) {
        int rr = i >> 5;
        int c4 = i & 31;
        int gr = row0 + rr;
        int xi = q[gr] + NUM_C * r[gr];
        ((float4*)(sV + rr * Dd))[c4] = ((const float4*)(Ev + (size_t)xi * Dd))[c4];
    }
    __syncthreads();

    const int wid = tid >> 5;
    const int cg  = tid & 31;

    u64 eA[4], eB[4], aA[4], aB[4];
    #pragma unroll
    for (int i = 0; i < 4; i++) { eA[i]=0ull; eB[i]=0ull; aA[i]=0ull; aB[i]=0ull; }

    for (int j = 0; j < Dd; j++) {
        float4 we = ((const float4*)(We + (size_t)j * Dd))[cg];
        float4 wa = ((const float4*)(Wa + (size_t)j * Dd))[cg];
        u64 weA = pack2(we.x, we.y), weB = pack2(we.z, we.w);
        u64 waA = pack2(wa.x, wa.y), waB = pack2(wa.z, wa.w);
        #pragma unroll
        for (int i = 0; i < 4; i++) {
            u64 b0 = bcast2(sV[(wid * 4 + i) * Dd + j]);
            eA[i] = fma2(b0, weA, eA[i]);
            eB[i] = fma2(b0, weB, eB[i]);
            aA[i] = fma2(b0, waA, aA[i]);
            aB[i] = fma2(b0, waB, aB[i]);
        }
    }

    float4 bev = ((const float4*)be)[cg];
    float4 bav = ((const float4*)ba)[cg];
    #pragma unroll
    for (int i = 0; i < 4; i++) {
        size_t row = (size_t)(row0 + wid * 4 + i);
        float2 ea = unpk(eA[i]), eb = unpk(eB[i]);
        float2 aa = unpk(aA[i]), ab = unpk(aB[i]);
        float4 ev, av;
        ev.x = -sigmoidf_(ea.x + bev.x);     // NEGATED for scan
        ev.y = -sigmoidf_(ea.y + bev.y);
        ev.z = -sigmoidf_(eb.x + bev.z);
        ev.w = -sigmoidf_(eb.y + bev.w);
        av.x = tanhf(aa.x + bav.x);
        av.y = tanhf(aa.y + bav.y);
        av.z = tanhf(ab.x + bav.z);
        av.w = tanhf(ab.y + bav.w);
        ((float4*)(g_e + row * Dd))[cg] = ev;
        ((float4*)(g_a + row * Dd))[cg] = av;
    }
}

// ---------------------------------------------------------------------------
// Kernel 2: sequential memory scan, f32x2 over m-pairs.
// grid (64 batches, 8 d-octants), 256 thr.
// mg = tid&15 owns 4 m-rows (2 packed pairs); dl = tid>>4 owns one d.
// Update: Mv <- Mv + w*(a + Mv*(-e))   [bitwise == reference ordering]
// ---------------------------------------------------------------------------
__global__ __launch_bounds__(256) void k_scan(const float* __restrict__ Mv0)
{
    const int b    = blockIdx.x;
    const int oct  = blockIdx.y;        // 0..7
    const int tid  = threadIdx.x;
    const int mg   = tid & 15;
    const int dl   = tid >> 4;          // 0..15
    const int d    = oct * 16 + dl;

    u64 Mv2[2];
    Mv2[0] = pack2(Mv0[(mg * 4 + 0) * Dd + d], Mv0[(mg * 4 + 1) * Dd + d]);
    Mv2[1] = pack2(Mv0[(mg * 4 + 2) * Dd + d], Mv0[(mg * 4 + 3) * Dd + d]);

    __shared__ float sW[CH][Mm];     // 4 KB
    __shared__ float sE[CH][16];     // 1 KB  (negated e)
    __shared__ float sA[CH][16];     // 1 KB

    const size_t rbase = (size_t)b * Ll;

    for (int c = 0; c < Ll / CH; c++) {
        __syncthreads();
        // stage w: CH*64/4 = 256 float4 — one per thread
        ((float4*)sW)[tid] = ((const float4*)(g_w + (rbase + (size_t)c * CH) * Mm))[tid];
        // stage e,a: 64 float4 each
        if (tid < 64) {
            int tt = tid >> 2, c4 = tid & 3;
            ((float4*)(sE[tt]))[c4] =
                ((const float4*)(g_e + (rbase + (size_t)c * CH + tt) * Dd + oct * 16))[c4];
        } else if (tid < 128) {
            int t2 = tid - 64;
            int tt = t2 >> 2, c4 = t2 & 3;
            ((float4*)(sA[tt]))[c4] =
                ((const float4*)(g_a + (rbase + (size_t)c * CH + tt) * Dd + oct * 16))[c4];
        }
        __syncthreads();

        #pragma unroll 4
        for (int tt = 0; tt < CH; tt++) {
            u64 e2 = bcast2(sE[tt][dl]);   // (-e, -e)
            u64 a2 = bcast2(sA[tt][dl]);

            ulonglong2 w2 = *(const ulonglong2*)(sW[tt] + mg * 4);

            u64 rp0 = 0ull, rp1 = 0ull;
            // pair 0
            rp0 = fma2(w2.x, Mv2[0], rp0);
            u64 u0 = fma2(Mv2[0], e2, a2);
            Mv2[0] = fma2(w2.x, u0, Mv2[0]);
            // pair 1
            rp1 = fma2(w2.y, Mv2[1], rp1);
            u64 u1 = fma2(Mv2[1], e2, a2);
            Mv2[1] = fma2(w2.y, u1, Mv2[1]);

            float rp = hsum2(add2(rp0, rp1));
            rp += __shfl_xor_sync(0xffffffffu, rp, 1);
            rp += __shfl_xor_sync(0xffffffffu, rp, 2);
            rp += __shfl_xor_sync(0xffffffffu, rp, 4);
            rp += __shfl_xor_sync(0xffffffffu, rp, 8);
            if (mg == 0)
                g_read[(rbase + (size_t)c * CH + tt) * Dd + d] = rp;
        }
    }
}

// ---------------------------------------------------------------------------
// Kernel 3: f = tanh([read | k] @ Wf + bf); p = sigmoid(f . Wp + bp)
// Pre-packed lane-dense weights: zero packing movs, dense 16B lane stride.
// ---------------------------------------------------------------------------
__global__ __launch_bounds__(256, 4) void k_post(
    const int* __restrict__ q,
    const float* __restrict__ Ek,
    const float* __restrict__ bf,
    const float* __restrict__ Wp, const float* __restrict__ bp,
    float* __restrict__ out)
{
    extern __shared__ float sm[];
    float* sR = sm;             // [32][Dd]
    float* sK = sm + 32 * Dd;   // [32][Dd]

    const int tid  = threadIdx.x;
    const int row0 = blockIdx.x * 32;

    for (int i = tid; i < 32 * (Dd / 4); i += 256) {
        int rr = i >> 5;
        int c4 = i & 31;
        int gr = row0 + rr;
        int qi = q[gr];
        ((float4*)(sK + rr * Dd))[c4] = ((const float4*)(Ek + (size_t)qi * Dd))[c4];
        ((float4*)(sR + rr * Dd))[c4] = ((const float4*)(g_read + (size_t)gr * Dd))[c4];
    }
    __syncthreads();

    const int wid = tid >> 5;
    const int cg  = tid & 31;

    u64 ac0[4], ac1[4], ac2[4], ac3[4];   // cols 4cg..4cg+3, halves over j-parity
    #pragma unroll
    for (int i = 0; i < 4; i++) { ac0[i]=0ull; ac1[i]=0ull; ac2[i]=0ull; ac3[i]=0ull; }

    const u64* wfp  = g_WfP;
    const u64* wfkp = g_WfkP;

    for (int jp = 0; jp < Dd / 2; jp++) {
        ulonglong2 wr01 = __ldg(((const ulonglong2*)(wfp  + jp * Dd))       + cg);
        ulonglong2 wr23 = __ldg(((const ulonglong2*)(wfp  + jp * Dd + 64))  + cg);
        ulonglong2 wk01 = __ldg(((const ulonglong2*)(wfkp + jp * Dd))       + cg);
        ulonglong2 wk23 = __ldg(((const ulonglong2*)(wfkp + jp * Dd + 64))  + cg);
        #pragma unroll
        for (int i = 0; i < 4; i++) {
            u64 rj2 = *(const u64*)(sR + (wid * 4 + i) * Dd + 2 * jp);
            u64 kj2 = *(const u64*)(sK + (wid * 4 + i) * Dd + 2 * jp);
            ac0[i] = fma2(rj2, wr01.x, ac0[i]);
            ac1[i] = fma2(rj2, wr01.y, ac1[i]);
            ac2[i] = fma2(rj2, wr23.x, ac2[i]);
            ac3[i] = fma2(rj2, wr23.y, ac3[i]);
            ac0[i] = fma2(kj2, wk01.x, ac0[i]);
            ac1[i] = fma2(kj2, wk01.y, ac1[i]);
            ac2[i] = fma2(kj2, wk23.x, ac2[i]);
            ac3[i] = fma2(kj2, wk23.y, ac3[i]);
        }
    }

    float4 bfv = ((const float4*)bf)[cg];
    float4 wp4 = ((const float4*)Wp)[cg];
    float bpv  = bp[0];

    #pragma unroll
    for (int i = 0; i < 4; i++) {
        float fx = tanhf(hsum2(ac0[i]) + bfv.x);
        float fy = tanhf(hsum2(ac1[i]) + bfv.y);
        float fz = tanhf(hsum2(ac2[i]) + bfv.z);
        float fw = tanhf(hsum2(ac3[i]) + bfv.w);
        float pp = fx * wp4.x + fy * wp4.y + fz * wp4.z + fw * wp4.w;
        #pragma unroll
        for (int o = 16; o > 0; o >>= 1)
            pp += __shfl_xor_sync(0xffffffffu, pp, o);
        if (cg == 0)
            out[row0 + wid * 4 + i] = sigmoidf_(pp + bpv);
    }
}

// ---------------------------------------------------------------------------
extern "C" void kernel_launch(void* const* d_in, const int* in_sizes, int n_in,
                              void* d_out, int out_size)
{
    const int*   q   = (const int*)  d_in[0];
    const int*   r   = (const int*)  d_in[1];
    const float* Ek  = (const float*)d_in[2];
    const float* Ev  = (const float*)d_in[3];
    const float* Mk  = (const float*)d_in[4];
    const float* Mv0 = (const float*)d_in[5];
    const float* We  = (const float*)d_in[6];
    const float* be  = (const float*)d_in[7];
    const float* Wa  = (const float*)d_in[8];
    const float* ba  = (const float*)d_in[9];
    const float* Wf  = (const float*)d_in[10];
    const float* bf  = (const float*)d_in[11];
    const float* Wp  = (const float*)d_in[12];
    const float* bp  = (const float*)d_in[13];
    float* out = (float*)d_out;

    const size_t smW  = (size_t)(64 * Dd + (Dd / 2) * Mm * 2) * sizeof(float); // 65536 B
    const size_t smEA = (size_t)(32 * Dd) * sizeof(float);                     // 16384 B
    const size_t smP  = (size_t)(2 * 32 * Dd) * sizeof(float);                 // 32768 B
    cudaFuncSetAttribute(k_w,    cudaFuncAttributeMaxDynamicSharedMemorySize, (int)smW);
    cudaFuncSetAttribute(k_ea,   cudaFuncAttributeMaxDynamicSharedMemorySize, (int)smEA);
    cudaFuncSetAttribute(k_post, cudaFuncAttributeMaxDynamicSharedMemorySize, (int)smP);

    k_prep<<<32, 256>>>(Wf);
    k_w   <<<NROWS / 64, 512, smW>>>(q, Ek, Mk);
    k_ea  <<<NROWS / 32, 256, smEA>>>(q, r, Ev, We, be, Wa, ba);
    k_scan<<<dim3(Bb, 8), 256>>>(Mv0);
    k_post<<<NROWS / 32, 256, smP>>>(q, Ek, bf, Wp, bp, out);
}

// round 15
// speedup vs baseline: 1.4205x; 1.4205x over previous
#include <cuda_runtime.h>
#include <cuda_bf16.h>
#include <cstddef>

// Problem constants
#define NUM_C 1000
#define Dd    128
#define Mm    64
#define Bb    64
#define Ll    512
#define NROWS (Bb * Ll)   // 32768
#define CH    16          // scan: steps staged per chunk
#define NC    (Ll / CH)   // 32 chunks

typedef unsigned long long u64;

// Scratch (static device globals — allocation-free)
__device__ float g_w[NROWS * Mm];
__device__ float g_e[NROWS * Dd];      // holds NEGATED erase gate (-e); scan-only consumer
__device__ float g_a[NROWS * Dd];
__device__ float g_read[NROWS * Dd];
// j-pair packed Wf, lane-dense layout (see k_prep)
__device__ u64 g_WfP [(Dd / 2) * Dd];
__device__ u64 g_WfkP[(Dd / 2) * Dd];

__device__ __forceinline__ float sigmoidf_(float x) {
    return 1.0f / (1.0f + __expf(-x));
}
__device__ __forceinline__ u64 bcast2(float x) {
    u64 r; asm("mov.b64 %0, {%1,%1};" : "=l"(r) : "f"(x)); return r;
}
__device__ __forceinline__ u64 pack2(float x, float y) {
    u64 r; asm("mov.b64 %0, {%1,%2};" : "=l"(r) : "f"(x), "f"(y)); return r;
}
__device__ __forceinline__ u64 fma2(u64 a, u64 b, u64 c) {
    u64 d; asm("fma.rn.f32x2 %0, %1, %2, %3;" : "=l"(d) : "l"(a), "l"(b), "l"(c)); return d;
}
__device__ __forceinline__ u64 add2(u64 a, u64 b) {
    u64 d; asm("add.rn.f32x2 %0, %1, %2;" : "=l"(d) : "l"(a), "l"(b)); return d;
}
__device__ __forceinline__ float2 unpk(u64 v) {
    float2 f; asm("mov.b64 {%0,%1}, %2;" : "=f"(f.x), "=f"(f.y) : "l"(v)); return f;
}
__device__ __forceinline__ float hsum2(u64 v) {
    float2 f = unpk(v); return f.x + f.y;
}

// ---------------------------------------------------------------------------
// Kernel 0: repack Wf into j-pair packed, lane-dense layout (both halves).
// ---------------------------------------------------------------------------
__global__ __launch_bounds__(256) void k_prep(const float* __restrict__ Wf)
{
    int idx = blockIdx.x * 256 + threadIdx.x;      // 0 .. 8191
    if (idx < (Dd / 2) * Dd) {
        int jp = idx >> 7;
        int s  = idx & 127;
        int col;
        if (s < 64) col = 4 * (s >> 1) + (s & 1);
        else { int s2 = s - 64; col = 4 * (s2 >> 1) + 2 + (s2 & 1); }
        g_WfP [idx] = pack2(Wf[(size_t)(2 * jp)      * Dd + col],
                            Wf[(size_t)(2 * jp + 1)  * Dd + col]);
        g_WfkP[idx] = pack2(Wf[(size_t)(Dd + 2 * jp)     * Dd + col],
                            Wf[(size_t)(Dd + 2 * jp + 1) * Dd + col]);
    }
}

// ---------------------------------------------------------------------------
// Kernel 1a: logits + softmax -> w.   512 threads, 64 rows/block.
// ---------------------------------------------------------------------------
__global__ __launch_bounds__(512, 2) void k_w(
    const int* __restrict__ q,
    const float* __restrict__ Ek,
    const float* __restrict__ Mk)
{
    extern __shared__ float sm[];
    float* sK   = sm;                 // [64][Dd]  32 KB
    float* sMkP = sm + 64 * Dd;       // [64 jp][64 slots float2]  32 KB

    const int tid  = threadIdx.x;
    const int row0 = blockIdx.x * 64;

    for (int i = tid; i < 64 * (Dd / 4); i += 512) {
        int rr = i >> 5;
        int c4 = i & 31;
        int qi = q[row0 + rr];
        ((float4*)(sK + rr * Dd))[c4] = ((const float4*)(Ek + (size_t)qi * Dd))[c4];
    }
    for (int i = tid; i < Mm * (Dd / 2); i += 512) {
        int s  = i & 63;
        int jp = i >> 6;
        ((float2*)sMkP)[jp * 64 + s] = *(const float2*)(Mk + (size_t)s * Dd + 2 * jp);
    }
    __syncthreads();

    const int wid = tid >> 5;
    const int cg  = tid & 31;

    u64 acc0[4], acc1[4];
    #pragma unroll
    for (int i = 0; i < 4; i++) { acc0[i] = 0ull; acc1[i] = 0ull; }

    for (int jp = 0; jp < Dd / 2; jp++) {
        ulonglong2 mk2 = ((const ulonglong2*)(sMkP + jp * 128))[cg];
        #pragma unroll
        for (int i = 0; i < 4; i++) {
            u64 k2 = *(const u64*)(sK + (wid * 4 + i) * Dd + 2 * jp);
            acc0[i] = fma2(k2, mk2.x, acc0[i]);
            acc1[i] = fma2(k2, mk2.y, acc1[i]);
        }
    }
    #pragma unroll
    for (int i = 0; i < 4; i++) {
        float l0 = hsum2(acc0[i]);
        float l1 = hsum2(acc1[i]);
        float mx = fmaxf(l0, l1);
        #pragma unroll
        for (int o = 16; o > 0; o >>= 1)
            mx = fmaxf(mx, __shfl_xor_sync(0xffffffffu, mx, o));
        float e0 = __expf(l0 - mx);
        float e1 = __expf(l1 - mx);
        float s = e0 + e1;
        #pragma unroll
        for (int o = 16; o > 0; o >>= 1)
            s += __shfl_xor_sync(0xffffffffu, s, o);
        float inv = 1.0f / s;
        *(float2*)(g_w + (size_t)(row0 + wid * 4 + i) * Mm + 2 * cg) =
            make_float2(e0 * inv, e1 * inv);
    }
}

// ---------------------------------------------------------------------------
// Kernel 1b: e = sigmoid(v We + be) [stored NEGATED], a = tanh(v Wa + ba).
// Software-pipelined weight loads (prefetch j+1 while FMAing j).
// ---------------------------------------------------------------------------
__global__ __launch_bounds__(256, 3) void k_ea(
    const int* __restrict__ q, const int* __restrict__ r,
    const float* __restrict__ Ev,
    const float* __restrict__ We, const float* __restrict__ be,
    const float* __restrict__ Wa, const float* __restrict__ ba)
{
    extern __shared__ float sm[];
    float* sV = sm;   // [32][Dd]  16 KB

    const int tid  = threadIdx.x;
    const int row0 = blockIdx.x * 32;

    for (int i = tid; i < 32 * (Dd / 4); i += 256) {
        int rr = i >> 5;
        int c4 = i & 31;
        int gr = row0 + rr;
        int xi = q[gr] + NUM_C * r[gr];
        ((float4*)(sV + rr * Dd))[c4] = ((const float4*)(Ev + (size_t)xi * Dd))[c4];
    }
    __syncthreads();

    const int wid = tid >> 5;
    const int cg  = tid & 31;

    u64 eA[4], eB[4], aA[4], aB[4];
    #pragma unroll
    for (int i = 0; i < 4; i++) { eA[i]=0ull; eB[i]=0ull; aA[i]=0ull; aB[i]=0ull; }

    float4 we = ((const float4*)(We))[cg];
    float4 wa = ((const float4*)(Wa))[cg];

    for (int j = 0; j < Dd; j++) {
        int jn = (j + 1 < Dd) ? j + 1 : j;
        float4 wen = ((const float4*)(We + (size_t)jn * Dd))[cg];
        float4 wan = ((const float4*)(Wa + (size_t)jn * Dd))[cg];

        u64 weA = pack2(we.x, we.y), weB = pack2(we.z, we.w);
        u64 waA = pack2(wa.x, wa.y), waB = pack2(wa.z, wa.w);
        #pragma unroll
        for (int i = 0; i < 4; i++) {
            u64 b0 = bcast2(sV[(wid * 4 + i) * Dd + j]);
            eA[i] = fma2(b0, weA, eA[i]);
            eB[i] = fma2(b0, weB, eB[i]);
            aA[i] = fma2(b0, waA, aA[i]);
            aB[i] = fma2(b0, waB, aB[i]);
        }
        we = wen; wa = wan;
    }

    float4 bev = ((const float4*)be)[cg];
    float4 bav = ((const float4*)ba)[cg];
    #pragma unroll
    for (int i = 0; i < 4; i++) {
        size_t row = (size_t)(row0 + wid * 4 + i);
        float2 ea = unpk(eA[i]), eb = unpk(eB[i]);
        float2 aa = unpk(aA[i]), ab = unpk(aB[i]);
        float4 ev, av;
        ev.x = -sigmoidf_(ea.x + bev.x);     // NEGATED for scan
        ev.y = -sigmoidf_(ea.y + bev.y);
        ev.z = -sigmoidf_(eb.x + bev.z);
        ev.w = -sigmoidf_(eb.y + bev.w);
        av.x = tanhf(aa.x + bav.x);
        av.y = tanhf(aa.y + bav.y);
        av.z = tanhf(ab.x + bav.z);
        av.w = tanhf(ab.y + bav.w);
        ((float4*)(g_e + row * Dd))[cg] = ev;
        ((float4*)(g_a + row * Dd))[cg] = av;
    }
}

// ---------------------------------------------------------------------------
// Kernel 2: sequential memory scan, f32x2 over m-pairs, DOUBLE-BUFFERED.
// grid (64 batches, 8 d-octants), 256 thr.
// mg = tid&15 owns 4 m-rows (2 packed pairs); dl = tid>>4 owns one d.
// Update: Mv <- Mv + w*(a + Mv*(-e))
// ---------------------------------------------------------------------------
__global__ __launch_bounds__(256) void k_scan(const float* __restrict__ Mv0)
{
    const int b    = blockIdx.x;
    const int oct  = blockIdx.y;        // 0..7
    const int tid  = threadIdx.x;
    const int mg   = tid & 15;
    const int dl   = tid >> 4;          // 0..15
    const int d    = oct * 16 + dl;

    u64 Mv2[2];
    Mv2[0] = pack2(Mv0[(mg * 4 + 0) * Dd + d], Mv0[(mg * 4 + 1) * Dd + d]);
    Mv2[1] = pack2(Mv0[(mg * 4 + 2) * Dd + d], Mv0[(mg * 4 + 3) * Dd + d]);

    __shared__ float sW[2][CH][Mm];   // 8 KB
    __shared__ float sE[2][CH][16];   // 2 KB  (negated e)
    __shared__ float sA[2][CH][16];   // 2 KB

    const size_t rbase = (size_t)b * Ll;

    // e/a staging role for this thread
    const bool  isE = (tid < 64);
    const bool  isA = (tid >= 64 && tid < 128);
    const int   t2  = tid & 63;
    const int   stt = t2 >> 2;
    const int   sc4 = t2 & 3;

    // Prologue: stage chunk 0 into buffer 0
    ((float4*)sW[0])[tid] = ((const float4*)(g_w + rbase * Mm))[tid];
    if (isE)
        ((float4*)(sE[0][stt]))[sc4] =
            ((const float4*)(g_e + (rbase + stt) * Dd + oct * 16))[sc4];
    else if (isA)
        ((float4*)(sA[0][stt]))[sc4] =
            ((const float4*)(g_a + (rbase + stt) * Dd + oct * 16))[sc4];
    __syncthreads();

    for (int c = 0; c < NC; c++) {
        const int cur = c & 1;
        const bool have = (c + 1 < NC);

        // Prefetch next chunk into registers (latency hidden by compute below)
        float4 pw, pea;
        if (have) {
            size_t nb = rbase + (size_t)(c + 1) * CH;
            pw = ((const float4*)(g_w + nb * Mm))[tid];
            if (isE)
                pea = ((const float4*)(g_e + (nb + stt) * Dd + oct * 16))[sc4];
            else if (isA)
                pea = ((const float4*)(g_a + (nb + stt) * Dd + oct * 16))[sc4];
        }

        #pragma unroll 4
        for (int tt = 0; tt < CH; tt++) {
            u64 e2 = bcast2(sE[cur][tt][dl]);   // (-e, -e)
            u64 a2 = bcast2(sA[cur][tt][dl]);

            ulonglong2 w2 = *(const ulonglong2*)(sW[cur][tt] + mg * 4);

            u64 rp0 = 0ull, rp1 = 0ull;
            rp0 = fma2(w2.x, Mv2[0], rp0);
            u64 u0 = fma2(Mv2[0], e2, a2);
            Mv2[0] = fma2(w2.x, u0, Mv2[0]);

            rp1 = fma2(w2.y, Mv2[1], rp1);
            u64 u1 = fma2(Mv2[1], e2, a2);
            Mv2[1] = fma2(w2.y, u1, Mv2[1]);

            float rp = hsum2(add2(rp0, rp1));
            rp += __shfl_xor_sync(0xffffffffu, rp, 1);
            rp += __shfl_xor_sync(0xffffffffu, rp, 2);
            rp += __shfl_xor_sync(0xffffffffu, rp, 4);
            rp += __shfl_xor_sync(0xffffffffu, rp, 8);
            if (mg == 0)
                g_read[(rbase + (size_t)c * CH + tt) * Dd + d] = rp;
        }

        // Store prefetched chunk into the other buffer, then one barrier.
        if (have) {
            const int nxt = cur ^ 1;
            ((float4*)sW[nxt])[tid] = pw;
            if (isE)      ((float4*)(sE[nxt][stt]))[sc4] = pea;
            else if (isA) ((float4*)(sA[nxt][stt]))[sc4] = pea;
        }
        __syncthreads();
    }
}

// ---------------------------------------------------------------------------
// Kernel 3: f = tanh([read | k] @ Wf + bf); p = sigmoid(f . Wp + bp)
// Pre-packed lane-dense weights + software-pipelined weight loads.
// ---------------------------------------------------------------------------
__global__ __launch_bounds__(256, 3) void k_post(
    const int* __restrict__ q,
    const float* __restrict__ Ek,
    const float* __restrict__ bf,
    const float* __restrict__ Wp, const float* __restrict__ bp,
    float* __restrict__ out)
{
    extern __shared__ float sm[];
    float* sR = sm;             // [32][Dd]
    float* sK = sm + 32 * Dd;   // [32][Dd]

    const int tid  = threadIdx.x;
    const int row0 = blockIdx.x * 32;

    for (int i = tid; i < 32 * (Dd / 4); i += 256) {
        int rr = i >> 5;
        int c4 = i & 31;
        int gr = row0 + rr;
        int qi = q[gr];
        ((float4*)(sK + rr * Dd))[c4] = ((const float4*)(Ek + (size_t)qi * Dd))[c4];
        ((float4*)(sR + rr * Dd))[c4] = ((const float4*)(g_read + (size_t)gr * Dd))[c4];
    }
    __syncthreads();

    const int wid = tid >> 5;
    const int cg  = tid & 31;

    u64 ac0[4], ac1[4], ac2[4], ac3[4];   // cols 4cg..4cg+3, halves over j-parity
    #pragma unroll
    for (int i = 0; i < 4; i++) { ac0[i]=0ull; ac1[i]=0ull; ac2[i]=0ull; ac3[i]=0ull; }

    const u64* wfp  = g_WfP;
    const u64* wfkp = g_WfkP;

    ulonglong2 wr01 = __ldg(((const ulonglong2*)(wfp ))      + cg);
    ulonglong2 wr23 = __ldg(((const ulonglong2*)(wfp  + 64)) + cg);
    ulonglong2 wk01 = __ldg(((const ulonglong2*)(wfkp))      + cg);
    ulonglong2 wk23 = __ldg(((const ulonglong2*)(wfkp + 64)) + cg);

    for (int jp = 0; jp < Dd / 2; jp++) {
        int jn = (jp + 1 < Dd / 2) ? jp + 1 : jp;
        ulonglong2 nr01 = __ldg(((const ulonglong2*)(wfp  + jn * Dd))       + cg);
        ulonglong2 nr23 = __ldg(((const ulonglong2*)(wfp  + jn * Dd + 64))  + cg);
        ulonglong2 nk01 = __ldg(((const ulonglong2*)(wfkp + jn * Dd))       + cg);
        ulonglong2 nk23 = __ldg(((const ulonglong2*)(wfkp + jn * Dd + 64))  + cg);

        #pragma unroll
        for (int i = 0; i < 4; i++) {
            u64 rj2 = *(const u64*)(sR + (wid * 4 + i) * Dd + 2 * jp);
            u64 kj2 = *(const u64*)(sK + (wid * 4 + i) * Dd + 2 * jp);
            ac0[i] = fma2(rj2, wr01.x, ac0[i]);
            ac1[i] = fma2(rj2, wr01.y, ac1[i]);
            ac2[i] = fma2(rj2, wr23.x, ac2[i]);
            ac3[i] = fma2(rj2, wr23.y, ac3[i]);
            ac0[i] = fma2(kj2, wk01.x, ac0[i]);
            ac1[i] = fma2(kj2, wk01.y, ac1[i]);
            ac2[i] = fma2(kj2, wk23.x, ac2[i]);
            ac3[i] = fma2(kj2, wk23.y, ac3[i]);
        }
        wr01 = nr01; wr23 = nr23; wk01 = nk01; wk23 = nk23;
    }

    float4 bfv = ((const float4*)bf)[cg];
    float4 wp4 = ((const float4*)Wp)[cg];
    float bpv  = bp[0];

    #pragma unroll
    for (int i = 0; i < 4; i++) {
        float fx = tanhf(hsum2(ac0[i]) + bfv.x);
        float fy = tanhf(hsum2(ac1[i]) + bfv.y);
        float fz = tanhf(hsum2(ac2[i]) + bfv.z);
        float fw = tanhf(hsum2(ac3[i]) + bfv.w);
        float pp = fx * wp4.x + fy * wp4.y + fz * wp4.z + fw * wp4.w;
        #pragma unroll
        for (int o = 16; o > 0; o >>= 1)
            pp += __shfl_xor_sync(0xffffffffu, pp, o);
        if (cg == 0)
            out[row0 + wid * 4 + i] = sigmoidf_(pp + bpv);
    }
}

// ---------------------------------------------------------------------------
extern "C" void kernel_launch(void* const* d_in, const int* in_sizes, int n_in,
                              void* d_out, int out_size)
{
    const int*   q   = (const int*)  d_in[0];
    const int*   r   = (const int*)  d_in[1];
    const float* Ek  = (const float*)d_in[2];
    const float* Ev  = (const float*)d_in[3];
    const float* Mk  = (const float*)d_in[4];
    const float* Mv0 = (const float*)d_in[5];
    const float* We  = (const float*)d_in[6];
    const float* be  = (const float*)d_in[7];
    const float* Wa  = (const float*)d_in[8];
    const float* ba  = (const float*)d_in[9];
    const float* Wf  = (const float*)d_in[10];
    const float* bf  = (const float*)d_in[11];
    const float* Wp  = (const float*)d_in[12];
    const float* bp  = (const float*)d_in[13];
    float* out = (float*)d_out;

    const size_t smW  = (size_t)(64 * Dd + (Dd / 2) * Mm * 2) * sizeof(float); // 65536 B
    const size_t smEA = (size_t)(32 * Dd) * sizeof(float);                     // 16384 B
    const size_t smP  = (size_t)(2 * 32 * Dd) * sizeof(float);                 // 32768 B
    cudaFuncSetAttribute(k_w,    cudaFuncAttributeMaxDynamicSharedMemorySize, (int)smW);
    cudaFuncSetAttribute(k_ea,   cudaFuncAttributeMaxDynamicSharedMemorySize, (int)smEA);
    cudaFuncSetAttribute(k_post, cudaFuncAttributeMaxDynamicSharedMemorySize, (int)smP);

    k_prep<<<32, 256>>>(Wf);
    k_w   <<<NROWS / 64, 512, smW>>>(q, Ek, Mk);
    k_ea  <<<NROWS / 32, 256, smEA>>>(q, r, Ev, We, be, Wa, ba);
    k_scan<<<dim3(Bb, 8), 256>>>(Mv0);
    k_post<<<NROWS / 32, 256, smP>>>(q, Ek, bf, Wp, bp, out);
}